// round 11
// baseline (speedup 1.0000x reference)
#include <cuda_runtime.h>
#include <math.h>
#include <stdint.h>

#define SN    255
#define B_    64
#define EMB   200
#define HID   300
#define NROWS (SN * B_)     // 16320
#define NC    1200
#define H_LD  304
#define KC2_E 7             // 32-k chunks for K=200 (pad 224)
#define KC2_U 10            // 32-k chunks for K=300 (pad 320)
#define K16_E 14
#define K16_U 20
#define NBG0  160
#define NBGI  128
#define NBGF  48
#define A_STRIDE 36         // smem A row stride in floats (BK=32 + pad)

// ---- device scratch (zero-initialized; padding cols stay 0) ----
__device__ float g_wx[NROWS * NC];
__device__ float g_H [NROWS * H_LD + 64];
__device__ float g_Hs[64 * B_ * H_LD + 64];
__device__ float g_C [NROWS * HID];
__device__ float g_Ti[64 * B_ * 900];
__device__ float g_Tf[128 * B_ * 300];
__device__ uint4 g_Bw_f[NBG0 * K16_E * 32];
__device__ uint4 g_Bi_f[NBGI * K16_U * 32];
__device__ uint4 g_Bf_f[NBGF * K16_U * 32];
__device__ float g_bias[NC];

__device__ __forceinline__ float sigmoidf(float x) { return 1.0f / (1.0f + expf(-x)); }
__device__ __forceinline__ uint32_t f2tf(float x) {
    uint32_t u; asm("cvt.rna.tf32.f32 %0, %1;" : "=r"(u) : "f"(x)); return u;
}

#define CPA16(dst, src) \
    asm volatile("cp.async.ca.shared.global [%0], [%1], 16;" :: "r"(dst), "l"(src))
#define CPA16Z(dst, src, sz) \
    asm volatile("cp.async.ca.shared.global [%0], [%1], 16, %2;" :: "r"(dst), "l"(src), "r"(sz))
#define CPCOMMIT() asm volatile("cp.async.commit_group;")
#define CPWAIT(n)  asm volatile("cp.async.wait_group %0;" :: "n"(n))

// ---------------------------------------------------------------------------
// Prep: pack three B matrices into tf32 fragment order (16-k chunks) + bias.
// ---------------------------------------------------------------------------
__global__ void prep_kernel(const float* __restrict__ W_iou, const float* __restrict__ W_f,
                            const float* __restrict__ U_iou, const float* __restrict__ U_f,
                            const float* __restrict__ b_iou, const float* __restrict__ b_f)
{
    int idx = blockIdx.x * blockDim.x + threadIdx.x;

    if (idx < NBG0 * K16_E * 32) {
        int ln = idx & 31, kch = (idx >> 5) % K16_E, nbg = idx / (32 * K16_E);
        int n = nbg * 8 + (ln >> 2), tk = ln & 3, kb = kch * 16;
        uint4 v; uint32_t* vp = (uint32_t*)&v;
        #pragma unroll
        for (int q = 0; q < 4; ++q) {
            int k = kb + q * 4 + tk;
            float f = 0.0f;
            if (k < EMB && n < NC)
                f = (n < 900) ? W_iou[k * 900 + n] : W_f[k * 300 + (n - 900)];
            vp[q] = f2tf(f);
        }
        g_Bw_f[idx] = v;
    }
    if (idx < NBGI * K16_U * 32) {
        int ln = idx & 31, kch = (idx >> 5) % K16_U, nbg = idx / (32 * K16_U);
        int n = nbg * 8 + (ln >> 2), tk = ln & 3, kb = kch * 16;
        uint4 v; uint32_t* vp = (uint32_t*)&v;
        #pragma unroll
        for (int q = 0; q < 4; ++q) {
            int k = kb + q * 4 + tk;
            float f = (k < HID && n < 900) ? U_iou[k * 900 + n] : 0.0f;
            vp[q] = f2tf(f);
        }
        g_Bi_f[idx] = v;
    }
    if (idx < NBGF * K16_U * 32) {
        int ln = idx & 31, kch = (idx >> 5) % K16_U, nbg = idx / (32 * K16_U);
        int n = nbg * 8 + (ln >> 2), tk = ln & 3, kb = kch * 16;
        uint4 v; uint32_t* vp = (uint32_t*)&v;
        #pragma unroll
        for (int q = 0; q < 4; ++q) {
            int k = kb + q * 4 + tk;
            float f = (k < HID && n < 300) ? U_f[k * 300 + n] : 0.0f;
            vp[q] = f2tf(f);
        }
        g_Bf_f[idx] = v;
    }
    if (idx < NC) g_bias[idx] = (idx < 900) ? b_iou[idx] : b_f[idx - 900];
}

#define MMA_STEP(ACC, AQ, B0, B1)                                              \
    asm("mma.sync.aligned.m16n8k8.row.col.f32.tf32.tf32.f32 "                  \
        "{%0,%1,%2,%3},{%4,%5,%6,%7},{%8,%9},{%0,%1,%2,%3};"                   \
        : "+f"((ACC)[0]), "+f"((ACC)[1]), "+f"((ACC)[2]), "+f"((ACC)[3])       \
        : "r"((AQ)[0]), "r"((AQ)[1]), "r"((AQ)[2]), "r"((AQ)[3]),              \
          "r"(B0), "r"(B1))

// ldmatrix.x4 on tf32 data in smem rows of A_STRIDE floats; COL = base column.
#define LDSM_A(AQ, ASBASE, R0, COL)                                            \
    do {                                                                       \
        const float* _p = (ASBASE) +                                           \
            ((R0) + (lane & 7) + ((lane >> 3) & 1) * 8) * A_STRIDE +           \
            (COL) + (lane >> 4) * 4;                                           \
        uint32_t _ad = (uint32_t)__cvta_generic_to_shared(_p);                 \
        asm volatile("ldmatrix.sync.aligned.m8n8.x4.shared.b16 "               \
                     "{%0,%1,%2,%3},[%4];"                                     \
                     : "=r"((AQ)[0]), "=r"((AQ)[1]), "=r"((AQ)[2]), "=r"((AQ)[3]) \
                     : "r"(_ad));                                              \
    } while (0)

// shared inner compute for one 32-k stage
#define COMPUTE_STAGE(AsS, BsS)                                                \
    do {                                                                       \
        _Pragma("unroll")                                                      \
        for (int sub = 0; sub < 2; ++sub) {                                    \
            uint32_t a[2][2][4];                                               \
            _Pragma("unroll")                                                  \
            for (int kb = 0; kb < 2; ++kb)                                     \
                _Pragma("unroll")                                              \
                for (int mf = 0; mf < 2; ++mf)                                 \
                    LDSM_A(a[kb][mf], (AsS), wm + mf * 16, sub * 16 + kb * 8); \
            _Pragma("unroll")                                                  \
            for (int nf = 0; nf < 8; ++nf) {                                   \
                uint4 bq = (BsS)[sub][nbW + nf][lane];                         \
                _Pragma("unroll")                                              \
                for (int mf = 0; mf < 2; ++mf) {                               \
                    MMA_STEP(acc[mf][nf], a[0][mf], bq.x, bq.y);               \
                    MMA_STEP(acc[mf][nf], a[1][mf], bq.z, bq.w);               \
                }                                                              \
            }                                                                  \
        }                                                                      \
    } while (0)

// smem sizes
#define A_STAGE_B (128 * A_STRIDE * 4)        // 18432
#define B_STAGE_B (2 * 16 * 32 * 16)          // 16384
#define SMEM_GEMM (3 * (A_STAGE_B + B_STAGE_B))

// ---------------------------------------------------------------------------
// gemm_wx: wx = [emb@W_iou+b | emb@W_f+b], M=16320, K=200, N=1200.
// ---------------------------------------------------------------------------
__global__ __launch_bounds__(256, 2) void gemm_wx(
    const float* __restrict__ embedTab, const int* __restrict__ xg)
{
    extern __shared__ char smem[];
    float (*As)[128][A_STRIDE]  = (float (*)[128][A_STRIDE])smem;
    uint4 (*Bs)[2][16][32]      = (uint4 (*)[2][16][32])(smem + 3 * A_STAGE_B);
    const float** arows         = (const float**)(smem + SMEM_GEMM);

    const int tid = threadIdx.x;
    const int rowBase = blockIdx.x * 128;
    const int colBase = blockIdx.y * 128;

    if (tid < 128) {
        int m = rowBase + tid;
        int mc = (m < NROWS) ? m : (NROWS - 1);
        arows[tid] = embedTab + (size_t)xg[mc] * EMB;
    }
    __syncthreads();

    const int lane = tid & 31, warp = tid >> 5;
    const int wm = (warp & 3) * 32, wn = (warp >> 2) * 64;
    const int nbW = wn >> 3;
    const int tg = lane >> 2, tk = lane & 3;
    const int nbgBase = colBase >> 3;

    // A fill coords: 4 rows per thread (same col chunk), warp = 4 rows x 128B
    const int arr = tid >> 3;           // base row 0..31
    const int acol = (tid & 7) * 4;     // float col of 16B chunk
    const float* aptr[4];
    #pragma unroll
    for (int i = 0; i < 4; ++i) aptr[i] = arows[arr + i * 32];

    float acc[2][8][4] = {};

#define FILL_WX(ST, KC)                                                         \
    do {                                                                        \
        int _k0 = (KC) * 32;                                                    \
        _Pragma("unroll")                                                       \
        for (int _i = 0; _i < 4; ++_i) {                                        \
            uint32_t _d = (uint32_t)__cvta_generic_to_shared(                   \
                &As[ST][arr + _i * 32][acol]);                                  \
            int _vb = EMB - (_k0 + acol);                                       \
            int _sz = (_vb >= 4) ? 16 : ((_vb > 0) ? _vb * 4 : 0);              \
            CPA16Z(_d, aptr[_i] + _k0 + acol, _sz);                             \
        }                                                                       \
        _Pragma("unroll")                                                       \
        for (int _i = 0; _i < 4; ++_i) {                                        \
            int _e = tid + _i * 256;                                            \
            int _sub = _e >> 9, _nb = (_e >> 5) & 15, _ln = _e & 31;            \
            uint32_t _d = (uint32_t)__cvta_generic_to_shared(&Bs[ST][_sub][_nb][_ln]); \
            CPA16(_d, g_Bw_f + ((size_t)(nbgBase + _nb) * K16_E + (KC) * 2 + _sub) * 32 + _ln); \
        }                                                                       \
        CPCOMMIT();                                                             \
    } while (0)

    FILL_WX(0, 0);
    FILL_WX(1, 1);

    for (int kc = 0; kc < KC2_E; ++kc) {
        const int s = kc % 3;
        if (kc + 1 < KC2_E) { CPWAIT(1); } else { CPWAIT(0); }
        __syncthreads();
        if (kc + 2 < KC2_E) FILL_WX((kc + 2) % 3, kc + 2);
        COMPUTE_STAGE(&As[s][0][0], Bs[s]);
    }
#undef FILL_WX

    #pragma unroll
    for (int mf = 0; mf < 2; ++mf)
        #pragma unroll
        for (int nf = 0; nf < 8; ++nf) {
            int row = rowBase + wm + mf * 16 + tg;
            int col = colBase + wn + nf * 8 + tk * 2;
            if (col < NC) {
                float b0 = g_bias[col], b1 = g_bias[col + 1];
                if (row < NROWS)
                    *(float2*)(g_wx + (size_t)row * NC + col) =
                        make_float2(acc[mf][nf][0] + b0, acc[mf][nf][1] + b1);
                if (row + 8 < NROWS)
                    *(float2*)(g_wx + (size_t)(row + 8) * NC + col) =
                        make_float2(acc[mf][nf][2] + b0, acc[mf][nf][3] + b1);
            }
        }
}

// ---------------------------------------------------------------------------
// level_gemm: packed 1D grid. Blocks [0, iouX*8): IOU (A=g_Hs, N=900->g_Ti);
// rest: F (A=H children, N=300->g_Tf). A reads overshoot into zero-padded /
// neighbor-row data; B fragments there are zero, so results are exact.
// ---------------------------------------------------------------------------
__global__ __launch_bounds__(256, 2) void level_gemm(int p0, int np, int iouX)
{
    extern __shared__ char smem[];
    float (*As)[128][A_STRIDE]  = (float (*)[128][A_STRIDE])smem;
    uint4 (*Bs)[2][16][32]      = (uint4 (*)[2][16][32])(smem + 3 * A_STAGE_B);

    const int tid = threadIdx.x;
    int id = blockIdx.x;
    const bool isF = (id >= iouX * 8);
    int xi, yi;
    if (isF) { id -= iouX * 8; xi = id % np; yi = id / np; }
    else     { xi = id % iouX; yi = id / iouX; }
    const int Mrows = isF ? np * 128 : np * 64;
    const int rowBase = xi * 128;
    const int colBase = yi * 128;
    const int Nout = isF ? 300 : 900;
    const uint4* gB = isF ? g_Bf_f : g_Bi_f;
    float* Cout = isF ? g_Tf : g_Ti;

    const int lane = tid & 31, warp = tid >> 5;
    const int wm = (warp & 3) * 32, wn = (warp >> 2) * 64;
    const int nbW = wn >> 3;
    const int tg = lane >> 2, tk = lane & 3;
    const int nbgBase = colBase >> 3;

    const int arr = tid >> 3;
    const int acol = (tid & 7) * 4;
    const float* aptr[4];
    #pragma unroll
    for (int i = 0; i < 4; ++i) {
        int r = rowBase + arr + i * 32;
        if (r >= Mrows) r = Mrows - 1;
        aptr[i] = isF ? g_H  + (size_t)((2 * p0 + 1) * B_ + r) * H_LD
                      : g_Hs + (size_t)r * H_LD;
    }

    float acc[2][8][4] = {};

#define FILL_LV(ST, KC)                                                         \
    do {                                                                        \
        int _k0 = (KC) * 32;                                                    \
        _Pragma("unroll")                                                       \
        for (int _i = 0; _i < 4; ++_i) {                                        \
            uint32_t _d = (uint32_t)__cvta_generic_to_shared(                   \
                &As[ST][arr + _i * 32][acol]);                                  \
            CPA16(_d, aptr[_i] + _k0 + acol);                                   \
        }                                                                       \
        _Pragma("unroll")                                                       \
        for (int _i = 0; _i < 4; ++_i) {                                        \
            int _e = tid + _i * 256;                                            \
            int _sub = _e >> 9, _nb = (_e >> 5) & 15, _ln = _e & 31;            \
            uint32_t _d = (uint32_t)__cvta_generic_to_shared(&Bs[ST][_sub][_nb][_ln]); \
            CPA16(_d, gB + ((size_t)(nbgBase + _nb) * K16_U + (KC) * 2 + _sub) * 32 + _ln); \
        }                                                                       \
        CPCOMMIT();                                                             \
    } while (0)

    FILL_LV(0, 0);
    FILL_LV(1, 1);

    for (int kc = 0; kc < KC2_U; ++kc) {
        const int s = kc % 3;
        if (kc + 1 < KC2_U) { CPWAIT(1); } else { CPWAIT(0); }
        __syncthreads();
        if (kc + 2 < KC2_U) FILL_LV((kc + 2) % 3, kc + 2);
        COMPUTE_STAGE(&As[s][0][0], Bs[s]);
    }
#undef FILL_LV

    #pragma unroll
    for (int mf = 0; mf < 2; ++mf)
        #pragma unroll
        for (int nf = 0; nf < 8; ++nf) {
            int row = rowBase + wm + mf * 16 + tg;
            int col = colBase + wn + nf * 8 + tk * 2;
            if (col < Nout) {
                if (row < Mrows)
                    *(float2*)(Cout + (size_t)row * Nout + col) =
                        make_float2(acc[mf][nf][0], acc[mf][nf][1]);
                if (row + 8 < Mrows)
                    *(float2*)(Cout + (size_t)(row + 8) * Nout + col) =
                        make_float2(acc[mf][nf][2], acc[mf][nf][3]);
            }
        }
}

// ---------------------------------------------------------------------------
// Leaves, sibling-paired: H, C for both leaves + Hs row for d=6.
// ---------------------------------------------------------------------------
__global__ void leaf_kernel()
{
    int idx = blockIdx.x * blockDim.x + threadIdx.x;
    if (idx >= 64 * B_ * HID) return;
    int n = idx % HID;
    int r = idx / HID;
    int b = r % B_;
    int j = r / B_;

    float hs = 0.0f;
    #pragma unroll
    for (int s = 0; s < 2; ++s) {
        int node = 127 + 2 * j + s;
        int row  = node * B_ + b;
        const float* wx = g_wx + (size_t)row * NC;
        float iv = sigmoidf(wx[n]);
        float ov = sigmoidf(wx[300 + n]);
        float uv = tanhf(wx[600 + n]);
        float c  = iv * uv;
        float h  = ov * tanhf(c);
        g_C[(size_t)row * HID + n] = c;
        g_H[(size_t)row * H_LD + n] = h;
        hs += h;
    }
    g_Hs[(size_t)r * H_LD + n] = hs;
}

// ---------------------------------------------------------------------------
// Pointwise gates
// ---------------------------------------------------------------------------
__device__ __forceinline__ float node_gate(int p0, int pi, int b, int n, float* cOut)
{
    int p = p0 + pi;
    const float* wx = g_wx + (size_t)(p * B_ + b) * NC;
    const float* ti = g_Ti + (size_t)(pi * B_ + b) * 900;
    float iv = sigmoidf(wx[n]       + ti[n]);
    float ov = sigmoidf(wx[300 + n] + ti[300 + n]);
    float uv = tanhf   (wx[600 + n] + ti[600 + n]);
    float wf = wx[900 + n];
    float fl = sigmoidf(wf + g_Tf[(size_t)((2 * pi    ) * B_ + b) * 300 + n]);
    float fr = sigmoidf(wf + g_Tf[(size_t)((2 * pi + 1) * B_ + b) * 300 + n]);
    int lc = 2 * p + 1, rc = 2 * p + 2;
    float fc = fl * g_C[(size_t)(lc * B_ + b) * HID + n]
             + fr * g_C[(size_t)(rc * B_ + b) * HID + n];
    float c = iv * uv + fc;
    *cOut = c;
    return ov * tanhf(c);
}

__global__ void level_pw_pair(int p0, int np)
{
    int idx = blockIdx.x * blockDim.x + threadIdx.x;
    int tot = (np >> 1) * B_ * HID;
    if (idx >= tot) return;
    int n = idx % HID;
    int r = idx / HID;
    int b = r % B_;
    int i = r / B_;

    float cL, cR;
    float hL = node_gate(p0, 2 * i,     b, n, &cL);
    float hR = node_gate(p0, 2 * i + 1, b, n, &cR);

    int pL = p0 + 2 * i, pR = pL + 1;
    g_C[(size_t)(pL * B_ + b) * HID + n] = cL;
    g_C[(size_t)(pR * B_ + b) * HID + n] = cR;
    g_H[(size_t)(pL * B_ + b) * H_LD + n] = hL;
    g_H[(size_t)(pR * B_ + b) * H_LD + n] = hR;
    g_Hs[(size_t)r * H_LD + n] = hL + hR;
}

__global__ void level_pw_root()
{
    int idx = blockIdx.x * blockDim.x + threadIdx.x;
    if (idx >= B_ * HID) return;
    int n = idx % HID;
    int b = idx / HID;
    float c;
    float h = node_gate(0, 0, b, n, &c);
    g_C[(size_t)b * HID + n] = c;
    g_H[(size_t)b * H_LD + n] = h;
}

// ---------------------------------------------------------------------------
// Output head
// ---------------------------------------------------------------------------
__global__ __launch_bounds__(64) void out_kernel(
    const float* __restrict__ W_out, const float* __restrict__ b_out,
    float* __restrict__ out)
{
    const int b = threadIdx.x;
    const float* h = g_H + (size_t)b * H_LD;
    float l0 = b_out[0], l1 = b_out[1];
    #pragma unroll 4
    for (int k = 0; k < HID; ++k) {
        float hv = h[k];
        l0 = fmaf(hv, W_out[k * 2 + 0], l0);
        l1 = fmaf(hv, W_out[k * 2 + 1], l1);
    }
    float m   = fmaxf(l0, l1);
    float lse = m + logf(expf(l0 - m) + expf(l1 - m));
    out[b * 2 + 0] = l0 - lse;
    out[b * 2 + 1] = l1 - lse;
}

// ---------------------------------------------------------------------------
extern "C" void kernel_launch(void* const* d_in, const int* in_sizes, int n_in,
                              void* d_out, int out_size)
{
    (void)in_sizes; (void)n_in; (void)out_size;
    const int*   x     = (const int*)  d_in[0];
    const float* embed = (const float*)d_in[3];
    const float* W_iou = (const float*)d_in[4];
    const float* U_iou = (const float*)d_in[5];
    const float* b_iou = (const float*)d_in[6];
    const float* W_f   = (const float*)d_in[7];
    const float* U_f   = (const float*)d_in[8];
    const float* b_f   = (const float*)d_in[9];
    const float* W_out = (const float*)d_in[10];
    const float* b_out = (const float*)d_in[11];

    const int SMEM_WX = SMEM_GEMM + 128 * 8;
    const int SMEM_LV = SMEM_GEMM;
    cudaFuncSetAttribute(gemm_wx,    cudaFuncAttributeMaxDynamicSharedMemorySize, SMEM_WX);
    cudaFuncSetAttribute(level_gemm, cudaFuncAttributeMaxDynamicSharedMemorySize, SMEM_LV);

    prep_kernel<<<(NBGI * K16_U * 32 + 255) / 256, 256>>>(W_iou, W_f, U_iou, U_f, b_iou, b_f);

    gemm_wx<<<dim3(128, 10), 256, SMEM_WX>>>(embed, x);
    leaf_kernel<<<(64 * B_ * HID + 255) / 256, 256>>>();

    for (int d = 6; d >= 1; --d) {
        int np = 1 << d;
        int p0 = np - 1;
        int iouX = (np + 1) >> 1;
        level_gemm<<<iouX * 8 + np * 3, 256, SMEM_LV>>>(p0, np, iouX);
        level_pw_pair<<<((np / 2) * B_ * HID + 255) / 256, 256>>>(p0, np);
    }
    level_gemm<<<1 * 8 + 1 * 3, 256, SMEM_LV>>>(0, 1, 1);
    level_pw_root<<<(B_ * HID + 255) / 256, 256>>>();

    out_kernel<<<1, 64>>>(W_out, b_out, (float*)d_out);
}

// round 12
// speedup vs baseline: 1.7356x; 1.7356x over previous
#include <cuda_runtime.h>
#include <math.h>
#include <stdint.h>

#define SN    255
#define B_    64
#define EMB   200
#define HID   300
#define NROWS (SN * B_)     // 16320
#define NC    1200
#define H_LD  304
#define KCH_E 13
#define KCH_U 19
#define NBG0  160
#define NBGI  128
#define NBGF  48

// ---- device scratch (zero-initialized at load; padding cols stay 0) ----
__device__ float g_wx[NROWS * NC];
__device__ float g_H [NROWS * H_LD + 64];
__device__ float g_Hs[64 * B_ * H_LD + 64];
__device__ float g_C [NROWS * HID];
__device__ float g_Ti[64 * B_ * 900];
__device__ float g_Tf[128 * B_ * 300];
__device__ uint4 g_Bw_f[NBG0 * KCH_E * 32];
__device__ uint4 g_Bi_f[NBGI * KCH_U * 32];
__device__ uint4 g_Bf_f[NBGF * KCH_U * 32];
__device__ float g_bias[NC];

__device__ __forceinline__ float sigmoidf(float x) { return 1.0f / (1.0f + expf(-x)); }
__device__ __forceinline__ uint32_t f2tf(float x) {
    uint32_t u; asm("cvt.rna.tf32.f32 %0, %1;" : "=r"(u) : "f"(x)); return u;
}

#define CPA16(dst, src) \
    asm volatile("cp.async.ca.shared.global [%0], [%1], 16;" :: "r"(dst), "l"(src))
#define CPA16Z(dst, src, sz) \
    asm volatile("cp.async.ca.shared.global [%0], [%1], 16, %2;" :: "r"(dst), "l"(src), "r"(sz))
#define CPCOMMIT() asm volatile("cp.async.commit_group;")
#define CPWAIT(n)  asm volatile("cp.async.wait_group %0;" :: "n"(n))

// ---------------------------------------------------------------------------
// Prep: pack three B matrices into tf32 fragment order + concat bias.
// ---------------------------------------------------------------------------
__global__ void prep_kernel(const float* __restrict__ W_iou, const float* __restrict__ W_f,
                            const float* __restrict__ U_iou, const float* __restrict__ U_f,
                            const float* __restrict__ b_iou, const float* __restrict__ b_f)
{
    int idx = blockIdx.x * blockDim.x + threadIdx.x;

    if (idx < NBG0 * KCH_E * 32) {
        int ln = idx & 31, kch = (idx >> 5) % KCH_E, nbg = idx / (32 * KCH_E);
        int n = nbg * 8 + (ln >> 2), tk = ln & 3, kb = kch * 16;
        uint4 v; uint32_t* vp = (uint32_t*)&v;
        #pragma unroll
        for (int q = 0; q < 4; ++q) {
            int k = kb + q * 4 + tk;
            float f = 0.0f;
            if (k < EMB && n < NC)
                f = (n < 900) ? W_iou[k * 900 + n] : W_f[k * 300 + (n - 900)];
            vp[q] = f2tf(f);
        }
        g_Bw_f[idx] = v;
    }
    if (idx < NBGI * KCH_U * 32) {
        int ln = idx & 31, kch = (idx >> 5) % KCH_U, nbg = idx / (32 * KCH_U);
        int n = nbg * 8 + (ln >> 2), tk = ln & 3, kb = kch * 16;
        uint4 v; uint32_t* vp = (uint32_t*)&v;
        #pragma unroll
        for (int q = 0; q < 4; ++q) {
            int k = kb + q * 4 + tk;
            float f = (k < HID && n < 900) ? U_iou[k * 900 + n] : 0.0f;
            vp[q] = f2tf(f);
        }
        g_Bi_f[idx] = v;
    }
    if (idx < NBGF * KCH_U * 32) {
        int ln = idx & 31, kch = (idx >> 5) % KCH_U, nbg = idx / (32 * KCH_U);
        int n = nbg * 8 + (ln >> 2), tk = ln & 3, kb = kch * 16;
        uint4 v; uint32_t* vp = (uint32_t*)&v;
        #pragma unroll
        for (int q = 0; q < 4; ++q) {
            int k = kb + q * 4 + tk;
            float f = (k < HID && n < 300) ? U_f[k * 300 + n] : 0.0f;
            vp[q] = f2tf(f);
        }
        g_Bf_f[idx] = v;
    }
    if (idx < NC) g_bias[idx] = (idx < 900) ? b_iou[idx] : b_f[idx - 900];
}

#define MMA_STEP(ACC, AQ, B0, B1)                                              \
    asm("mma.sync.aligned.m16n8k8.row.col.f32.tf32.tf32.f32 "                  \
        "{%0,%1,%2,%3},{%4,%5,%6,%7},{%8,%9},{%0,%1,%2,%3};"                   \
        : "+f"((ACC)[0]), "+f"((ACC)[1]), "+f"((ACC)[2]), "+f"((ACC)[3])       \
        : "r"((AQ)[0]), "r"((AQ)[1]), "r"((AQ)[2]), "r"((AQ)[3]),              \
          "r"(B0), "r"(B1))

// ldmatrix.x4 on tf32 data: one instr per (kb,mf) A fragment; stride 20 floats.
#define LDSM_A(AQ, ASBASE, R0, KB)                                             \
    do {                                                                       \
        const float* _p = (ASBASE) +                                           \
            ((R0) + (lane & 7) + ((lane >> 3) & 1) * 8) * 20 +                 \
            (KB) * 8 + (lane >> 4) * 4;                                        \
        uint32_t _ad = (uint32_t)__cvta_generic_to_shared(_p);                 \
        asm volatile("ldmatrix.sync.aligned.m8n8.x4.shared.b16 "               \
                     "{%0,%1,%2,%3},[%4];"                                     \
                     : "=r"((AQ)[0]), "=r"((AQ)[1]), "=r"((AQ)[2]), "=r"((AQ)[3]) \
                     : "r"(_ad));                                              \
    } while (0)

// ---------------------------------------------------------------------------
// gemm_wx: wx rows [rowOff, rowOff+Mpart) = emb @ [W_iou|W_f] + bias.
// BK=16, 3-stage cp.async, 1 sync/iter, LDSM A path (R10 configuration).
// ---------------------------------------------------------------------------
__global__ __launch_bounds__(256, 2) void gemm_wx(
    const float* __restrict__ embedTab, const int* __restrict__ xg,
    int rowOff, int Mpart)
{
    extern __shared__ char smem[];
    float (*As)[128][20] = (float (*)[128][20])smem;
    uint4 (*Bs)[16][32]  = (uint4 (*)[16][32])(smem + 3 * 128 * 80);
    const float** arows  = (const float**)(smem + 3 * 128 * 80 + 3 * 16 * 32 * 16);

    const int tid = threadIdx.x;
    const int rowBase = rowOff + blockIdx.x * 128;
    const int colBase = blockIdx.y * 128;
    const int Mend = rowOff + Mpart;

    if (tid < 128) {
        int m = rowBase + tid;
        int mc = (m < Mend) ? m : (Mend - 1);
        arows[tid] = embedTab + (size_t)xg[mc] * EMB;
    }
    __syncthreads();

    const int lane = tid & 31, warp = tid >> 5;
    const int wm = (warp & 3) * 32, wn = (warp >> 2) * 64;
    const int nbW = wn >> 3;
    const int tg = lane >> 2, tk = lane & 3;
    const int nbgBase = colBase >> 3;

    float acc[2][8][4] = {};

#define FILL_WX(ST, KC)                                                         \
    do {                                                                        \
        int _k0 = (KC) * 16;                                                    \
        _Pragma("unroll")                                                       \
        for (int _i = 0; _i < 2; ++_i) {                                        \
            int _e = tid + _i * 256, _r = _e >> 2, _c = _e & 3;                 \
            uint32_t _d = (uint32_t)__cvta_generic_to_shared(&As[ST][_r][_c*4]);\
            const float* _s = arows[_r] + _k0 + _c * 4;                         \
            int _vb = EMB - (_k0 + _c * 4);                                     \
            int _sz = (_vb >= 4) ? 16 : ((_vb > 0) ? _vb * 4 : 0);              \
            CPA16Z(_d, _s, _sz);                                                \
        }                                                                       \
        _Pragma("unroll")                                                       \
        for (int _i = 0; _i < 2; ++_i) {                                        \
            int _e = tid + _i * 256, _nb = _e >> 5, _ln = _e & 31;              \
            uint32_t _d = (uint32_t)__cvta_generic_to_shared(&Bs[ST][_nb][_ln]);\
            CPA16(_d, g_Bw_f + ((size_t)(nbgBase + _nb) * KCH_E + (KC)) * 32 + _ln); \
        }                                                                       \
        CPCOMMIT();                                                             \
    } while (0)

    FILL_WX(0, 0);
    FILL_WX(1, 1);

    for (int kch = 0; kch < KCH_E; ++kch) {
        const int s = kch % 3;
        if (kch + 1 < KCH_E) { CPWAIT(1); } else { CPWAIT(0); }
        __syncthreads();
        if (kch + 2 < KCH_E) FILL_WX((kch + 2) % 3, kch + 2);

        uint32_t a[2][2][4];
        #pragma unroll
        for (int kb = 0; kb < 2; ++kb)
            #pragma unroll
            for (int mf = 0; mf < 2; ++mf)
                LDSM_A(a[kb][mf], &As[s][0][0], wm + mf * 16, kb);

        #pragma unroll
        for (int nf = 0; nf < 8; ++nf) {
            uint4 bq = Bs[s][nbW + nf][lane];
            #pragma unroll
            for (int mf = 0; mf < 2; ++mf) {
                MMA_STEP(acc[mf][nf], a[0][mf], bq.x, bq.y);
                MMA_STEP(acc[mf][nf], a[1][mf], bq.z, bq.w);
            }
        }
    }
#undef FILL_WX

    #pragma unroll
    for (int mf = 0; mf < 2; ++mf)
        #pragma unroll
        for (int nf = 0; nf < 8; ++nf) {
            int row = rowBase + wm + mf * 16 + tg;
            int col = colBase + wn + nf * 8 + tk * 2;
            if (col < NC) {
                float b0 = g_bias[col], b1 = g_bias[col + 1];
                if (row < Mend)
                    *(float2*)(g_wx + (size_t)row * NC + col) =
                        make_float2(acc[mf][nf][0] + b0, acc[mf][nf][1] + b1);
                if (row + 8 < Mend)
                    *(float2*)(g_wx + (size_t)(row + 8) * NC + col) =
                        make_float2(acc[mf][nf][2] + b0, acc[mf][nf][3] + b1);
            }
        }
}

// ---------------------------------------------------------------------------
// level_gemm: fused per-level GEMMs (R10 configuration).
//  blockIdx.y < 8 : IOU: A = g_Hs (M=np*64), B=U_iou, N=900 -> g_Ti
//  blockIdx.y >= 8: F:   A = H children (M=np*128), B=U_f, N=300 -> g_Tf
// ---------------------------------------------------------------------------
__global__ __launch_bounds__(256, 2) void level_gemm(int p0, int np)
{
    extern __shared__ char smem[];
    float (*As)[128][20] = (float (*)[128][20])smem;
    uint4 (*Bs)[16][32]  = (uint4 (*)[16][32])(smem + 3 * 128 * 80);

    const int tid = threadIdx.x;
    const bool isF = (blockIdx.y >= 8);
    const int Mrows = isF ? np * 128 : np * 64;
    const int rowBase = blockIdx.x * 128;
    if (rowBase >= Mrows) return;
    const int colBase = (isF ? (blockIdx.y - 8) : blockIdx.y) * 128;
    const int Nout = isF ? 300 : 900;
    const uint4* gB = isF ? g_Bf_f : g_Bi_f;
    float* Cout = isF ? g_Tf : g_Ti;

    const int lane = tid & 31, warp = tid >> 5;
    const int wm = (warp & 3) * 32, wn = (warp >> 2) * 64;
    const int nbW = wn >> 3;
    const int tg = lane >> 2, tk = lane & 3;
    const int nbgBase = colBase >> 3;

    const int ar = tid >> 1;
    const int ac = (tid & 1) << 1;
    int arow = rowBase + ar; if (arow >= Mrows) arow = Mrows - 1;
    const float* asrc = isF
        ? g_H  + (size_t)((2 * p0 + 1) * B_ + arow) * H_LD
        : g_Hs + (size_t)arow * H_LD;

    float acc[2][8][4] = {};

#define FILL_LV(ST, KC)                                                         \
    do {                                                                        \
        int _k0 = (KC) * 16;                                                    \
        _Pragma("unroll")                                                       \
        for (int _i = 0; _i < 2; ++_i) {                                        \
            int _c = ac + _i;                                                   \
            uint32_t _d = (uint32_t)__cvta_generic_to_shared(&As[ST][ar][_c*4]);\
            CPA16(_d, asrc + _k0 + _c * 4);                                     \
        }                                                                       \
        _Pragma("unroll")                                                       \
        for (int _i = 0; _i < 2; ++_i) {                                        \
            int _e = tid + _i * 256, _nb = _e >> 5, _ln = _e & 31;              \
            uint32_t _d = (uint32_t)__cvta_generic_to_shared(&Bs[ST][_nb][_ln]);\
            CPA16(_d, gB + ((size_t)(nbgBase + _nb) * KCH_U + (KC)) * 32 + _ln);\
        }                                                                       \
        CPCOMMIT();                                                             \
    } while (0)

    FILL_LV(0, 0);
    FILL_LV(1, 1);

    for (int kch = 0; kch < KCH_U; ++kch) {
        const int s = kch % 3;
        if (kch + 1 < KCH_U) { CPWAIT(1); } else { CPWAIT(0); }
        __syncthreads();
        if (kch + 2 < KCH_U) FILL_LV((kch + 2) % 3, kch + 2);

        uint32_t a[2][2][4];
        #pragma unroll
        for (int kb = 0; kb < 2; ++kb)
            #pragma unroll
            for (int mf = 0; mf < 2; ++mf)
                LDSM_A(a[kb][mf], &As[s][0][0], wm + mf * 16, kb);

        #pragma unroll
        for (int nf = 0; nf < 8; ++nf) {
            uint4 bq = Bs[s][nbW + nf][lane];
            #pragma unroll
            for (int mf = 0; mf < 2; ++mf) {
                MMA_STEP(acc[mf][nf], a[0][mf], bq.x, bq.y);
                MMA_STEP(acc[mf][nf], a[1][mf], bq.z, bq.w);
            }
        }
    }
#undef FILL_LV

    #pragma unroll
    for (int mf = 0; mf < 2; ++mf)
        #pragma unroll
        for (int nf = 0; nf < 8; ++nf) {
            int row = rowBase + wm + mf * 16 + tg;
            int col = colBase + wn + nf * 8 + tk * 2;
            if (col < Nout) {
                if (row < Mrows)
                    *(float2*)(Cout + (size_t)row * Nout + col) =
                        make_float2(acc[mf][nf][0], acc[mf][nf][1]);
                if (row + 8 < Mrows)
                    *(float2*)(Cout + (size_t)(row + 8) * Nout + col) =
                        make_float2(acc[mf][nf][2], acc[mf][nf][3]);
            }
        }
}

// ---------------------------------------------------------------------------
// Leaves, sibling-paired: H, C for both leaves + Hs row for d=6.
// ---------------------------------------------------------------------------
__global__ void leaf_kernel()
{
    int idx = blockIdx.x * blockDim.x + threadIdx.x;
    if (idx >= 64 * B_ * HID) return;
    int n = idx % HID;
    int r = idx / HID;
    int b = r % B_;
    int j = r / B_;

    float hs = 0.0f;
    #pragma unroll
    for (int s = 0; s < 2; ++s) {
        int node = 127 + 2 * j + s;
        int row  = node * B_ + b;
        const float* wx = g_wx + (size_t)row * NC;
        float iv = sigmoidf(wx[n]);
        float ov = sigmoidf(wx[300 + n]);
        float uv = tanhf(wx[600 + n]);
        float c  = iv * uv;
        float h  = ov * tanhf(c);
        g_C[(size_t)row * HID + n] = c;
        g_H[(size_t)row * H_LD + n] = h;
        hs += h;
    }
    g_Hs[(size_t)r * H_LD + n] = hs;
}

// ---------------------------------------------------------------------------
// Pointwise gates
// ---------------------------------------------------------------------------
__device__ __forceinline__ float node_gate(int p0, int pi, int b, int n, float* cOut)
{
    int p = p0 + pi;
    const float* wx = g_wx + (size_t)(p * B_ + b) * NC;
    const float* ti = g_Ti + (size_t)(pi * B_ + b) * 900;
    float iv = sigmoidf(wx[n]       + ti[n]);
    float ov = sigmoidf(wx[300 + n] + ti[300 + n]);
    float uv = tanhf   (wx[600 + n] + ti[600 + n]);
    float wf = wx[900 + n];
    float fl = sigmoidf(wf + g_Tf[(size_t)((2 * pi    ) * B_ + b) * 300 + n]);
    float fr = sigmoidf(wf + g_Tf[(size_t)((2 * pi + 1) * B_ + b) * 300 + n]);
    int lc = 2 * p + 1, rc = 2 * p + 2;
    float fc = fl * g_C[(size_t)(lc * B_ + b) * HID + n]
             + fr * g_C[(size_t)(rc * B_ + b) * HID + n];
    float c = iv * uv + fc;
    *cOut = c;
    return ov * tanhf(c);
}

__global__ void level_pw_pair(int p0, int np)
{
    int idx = blockIdx.x * blockDim.x + threadIdx.x;
    int tot = (np >> 1) * B_ * HID;
    if (idx >= tot) return;
    int n = idx % HID;
    int r = idx / HID;
    int b = r % B_;
    int i = r / B_;

    float cL, cR;
    float hL = node_gate(p0, 2 * i,     b, n, &cL);
    float hR = node_gate(p0, 2 * i + 1, b, n, &cR);

    int pL = p0 + 2 * i, pR = pL + 1;
    g_C[(size_t)(pL * B_ + b) * HID + n] = cL;
    g_C[(size_t)(pR * B_ + b) * HID + n] = cR;
    g_H[(size_t)(pL * B_ + b) * H_LD + n] = hL;
    g_H[(size_t)(pR * B_ + b) * H_LD + n] = hR;
    g_Hs[(size_t)r * H_LD + n] = hL + hR;
}

__global__ void level_pw_root()
{
    int idx = blockIdx.x * blockDim.x + threadIdx.x;
    if (idx >= B_ * HID) return;
    int n = idx % HID;
    int b = idx / HID;
    float c;
    float h = node_gate(0, 0, b, n, &c);
    g_C[(size_t)b * HID + n] = c;
    g_H[(size_t)b * H_LD + n] = h;
}

// ---------------------------------------------------------------------------
// Output head
// ---------------------------------------------------------------------------
__global__ __launch_bounds__(64) void out_kernel(
    const float* __restrict__ W_out, const float* __restrict__ b_out,
    float* __restrict__ out)
{
    const int b = threadIdx.x;
    const float* h = g_H + (size_t)b * H_LD;
    float l0 = b_out[0], l1 = b_out[1];
    #pragma unroll 4
    for (int k = 0; k < HID; ++k) {
        float hv = h[k];
        l0 = fmaf(hv, W_out[k * 2 + 0], l0);
        l1 = fmaf(hv, W_out[k * 2 + 1], l1);
    }
    float m   = fmaxf(l0, l1);
    float lse = m + logf(expf(l0 - m) + expf(l1 - m));
    out[b * 2 + 0] = l0 - lse;
    out[b * 2 + 1] = l1 - lse;
}

// ---------------------------------------------------------------------------
extern "C" void kernel_launch(void* const* d_in, const int* in_sizes, int n_in,
                              void* d_out, int out_size)
{
    (void)in_sizes; (void)n_in; (void)out_size;
    const int*   x     = (const int*)  d_in[0];
    const float* embed = (const float*)d_in[3];
    const float* W_iou = (const float*)d_in[4];
    const float* U_iou = (const float*)d_in[5];
    const float* b_iou = (const float*)d_in[6];
    const float* W_f   = (const float*)d_in[7];
    const float* U_f   = (const float*)d_in[8];
    const float* b_f   = (const float*)d_in[9];
    const float* W_out = (const float*)d_in[10];
    const float* b_out = (const float*)d_in[11];

    const int SMEM_WX = 3 * 128 * 80 + 3 * 16 * 32 * 16 + 128 * 8;
    const int SMEM_LV = 3 * 128 * 80 + 3 * 16 * 32 * 16;

    static cudaStream_t s2 = 0;
    static cudaEvent_t evFork = 0, evJoin = 0;
    static int inited = 0;
    if (!inited) {
        cudaFuncSetAttribute(gemm_wx,    cudaFuncAttributeMaxDynamicSharedMemorySize, SMEM_WX);
        cudaFuncSetAttribute(level_gemm, cudaFuncAttributeMaxDynamicSharedMemorySize, SMEM_LV);
        cudaStreamCreateWithFlags(&s2, cudaStreamNonBlocking);
        cudaEventCreateWithFlags(&evFork, cudaEventDisableTiming);
        cudaEventCreateWithFlags(&evJoin, cudaEventDisableTiming);
        inited = 1;
    }

    prep_kernel<<<(NBGI * KCH_U * 32 + 255) / 256, 256>>>(W_iou, W_f, U_iou, U_f, b_iou, b_f);

    // Fork: internal-node wx (rows 0..8127) on s2, overlapped with the leaf path.
    cudaEventRecord(evFork, 0);
    cudaStreamWaitEvent(s2, evFork, 0);
    gemm_wx<<<dim3(64, 10), 256, SMEM_WX, s2>>>(embed, x, 0, 127 * B_);
    cudaEventRecord(evJoin, s2);

    // Leaf path on stream 0: leaf-node wx (rows 8128..16319), gates, d=6 GEMM.
    gemm_wx<<<dim3(64, 10), 256, SMEM_WX>>>(embed, x, 127 * B_, 128 * B_);
    leaf_kernel<<<(64 * B_ * HID + 255) / 256, 256>>>();

    {
        int np = 64, p0 = 63;
        level_gemm<<<dim3(np, 11), 256, SMEM_LV>>>(p0, np);
        // Join: pw at d=6 reads wx of internal nodes (rows < 8128).
        cudaStreamWaitEvent(0, evJoin, 0);
        level_pw_pair<<<((np / 2) * B_ * HID + 255) / 256, 256>>>(p0, np);
    }

    for (int d = 5; d >= 1; --d) {
        int np = 1 << d;
        int p0 = np - 1;
        level_gemm<<<dim3(np, 11), 256, SMEM_LV>>>(p0, np);
        level_pw_pair<<<((np / 2) * B_ * HID + 255) / 256, 256>>>(p0, np);
    }
    level_gemm<<<dim3(1, 11), 256, SMEM_LV>>>(0, 1);
    level_pw_root<<<(B_ * HID + 255) / 256, 256>>>();

    out_kernel<<<1, 64>>>(W_out, b_out, (float*)d_out);
}

// round 13
// speedup vs baseline: 2.0649x; 1.1897x over previous
#include <cuda_runtime.h>
#include <math.h>
#include <stdint.h>

#define SN    255
#define B_    64
#define EMB   200
#define HID   300
#define NROWS (SN * B_)     // 16320
#define NC    1200
#define H_LD  304
#define KCH_E 13
#define KCH_U 19
#define NBG0  160
#define NBGI  128
#define NBGF  48

// ---- device scratch (zero-initialized at load; padding cols stay 0) ----
__device__ float g_wx[NROWS * NC];
__device__ float g_H [NROWS * H_LD + 64];
__device__ float g_Hs[64 * B_ * H_LD + 64];
__device__ float g_C [NROWS * HID];
__device__ float g_Ti[64 * B_ * 900];
__device__ float g_Tf[128 * B_ * 300];
__device__ uint4 g_Bw_f[NBG0 * KCH_E * 32];
__device__ uint4 g_Bi_f[NBGI * KCH_U * 32];
__device__ uint4 g_Bf_f[NBGF * KCH_U * 32];
__device__ float g_bias[NC];

__device__ __forceinline__ uint32_t f2tf(float x) {
    uint32_t u; asm("cvt.rna.tf32.f32 %0, %1;" : "=r"(u) : "f"(x)); return u;
}

// ---- fast gates (2-ulp __expf; error ~1e-7 rel, safe vs tf32's 1e-5) ----
__device__ __forceinline__ float fsig(float x) {
    return __fdividef(1.0f, 1.0f + __expf(-x));
}
__device__ __forceinline__ float ftanh(float x) {
    float t = __expf(-2.0f * fabsf(x));
    float r = __fdividef(1.0f - t, 1.0f + t);
    return copysignf(r, x);
}
__device__ __forceinline__ float4 f4add(float4 a, float4 b) {
    return make_float4(a.x + b.x, a.y + b.y, a.z + b.z, a.w + b.w);
}
__device__ __forceinline__ float4 f4sig(float4 a) {
    return make_float4(fsig(a.x), fsig(a.y), fsig(a.z), fsig(a.w));
}
__device__ __forceinline__ float4 f4tanh(float4 a) {
    return make_float4(ftanh(a.x), ftanh(a.y), ftanh(a.z), ftanh(a.w));
}
__device__ __forceinline__ float4 f4mul(float4 a, float4 b) {
    return make_float4(a.x * b.x, a.y * b.y, a.z * b.z, a.w * b.w);
}
__device__ __forceinline__ float4 f4fma(float4 a, float4 b, float4 c) {
    return make_float4(fmaf(a.x, b.x, c.x), fmaf(a.y, b.y, c.y),
                       fmaf(a.z, b.z, c.z), fmaf(a.w, b.w, c.w));
}

#define CPA16(dst, src) \
    asm volatile("cp.async.ca.shared.global [%0], [%1], 16;" :: "r"(dst), "l"(src))
#define CPA16Z(dst, src, sz) \
    asm volatile("cp.async.ca.shared.global [%0], [%1], 16, %2;" :: "r"(dst), "l"(src), "r"(sz))
#define CPCOMMIT() asm volatile("cp.async.commit_group;")
#define CPWAIT(n)  asm volatile("cp.async.wait_group %0;" :: "n"(n))

// ---------------------------------------------------------------------------
// Prep: pack three B matrices into tf32 fragment order + concat bias.
// ---------------------------------------------------------------------------
__global__ void prep_kernel(const float* __restrict__ W_iou, const float* __restrict__ W_f,
                            const float* __restrict__ U_iou, const float* __restrict__ U_f,
                            const float* __restrict__ b_iou, const float* __restrict__ b_f)
{
    int idx = blockIdx.x * blockDim.x + threadIdx.x;

    if (idx < NBG0 * KCH_E * 32) {
        int ln = idx & 31, kch = (idx >> 5) % KCH_E, nbg = idx / (32 * KCH_E);
        int n = nbg * 8 + (ln >> 2), tk = ln & 3, kb = kch * 16;
        uint4 v; uint32_t* vp = (uint32_t*)&v;
        #pragma unroll
        for (int q = 0; q < 4; ++q) {
            int k = kb + q * 4 + tk;
            float f = 0.0f;
            if (k < EMB && n < NC)
                f = (n < 900) ? W_iou[k * 900 + n] : W_f[k * 300 + (n - 900)];
            vp[q] = f2tf(f);
        }
        g_Bw_f[idx] = v;
    }
    if (idx < NBGI * KCH_U * 32) {
        int ln = idx & 31, kch = (idx >> 5) % KCH_U, nbg = idx / (32 * KCH_U);
        int n = nbg * 8 + (ln >> 2), tk = ln & 3, kb = kch * 16;
        uint4 v; uint32_t* vp = (uint32_t*)&v;
        #pragma unroll
        for (int q = 0; q < 4; ++q) {
            int k = kb + q * 4 + tk;
            float f = (k < HID && n < 900) ? U_iou[k * 900 + n] : 0.0f;
            vp[q] = f2tf(f);
        }
        g_Bi_f[idx] = v;
    }
    if (idx < NBGF * KCH_U * 32) {
        int ln = idx & 31, kch = (idx >> 5) % KCH_U, nbg = idx / (32 * KCH_U);
        int n = nbg * 8 + (ln >> 2), tk = ln & 3, kb = kch * 16;
        uint4 v; uint32_t* vp = (uint32_t*)&v;
        #pragma unroll
        for (int q = 0; q < 4; ++q) {
            int k = kb + q * 4 + tk;
            float f = (k < HID && n < 300) ? U_f[k * 300 + n] : 0.0f;
            vp[q] = f2tf(f);
        }
        g_Bf_f[idx] = v;
    }
    if (idx < NC) g_bias[idx] = (idx < 900) ? b_iou[idx] : b_f[idx - 900];
}

#define MMA_STEP(ACC, AQ, B0, B1)                                              \
    asm("mma.sync.aligned.m16n8k8.row.col.f32.tf32.tf32.f32 "                  \
        "{%0,%1,%2,%3},{%4,%5,%6,%7},{%8,%9},{%0,%1,%2,%3};"                   \
        : "+f"((ACC)[0]), "+f"((ACC)[1]), "+f"((ACC)[2]), "+f"((ACC)[3])       \
        : "r"((AQ)[0]), "r"((AQ)[1]), "r"((AQ)[2]), "r"((AQ)[3]),              \
          "r"(B0), "r"(B1))

#define LDSM_A(AQ, ASBASE, R0, KB)                                             \
    do {                                                                       \
        const float* _p = (ASBASE) +                                           \
            ((R0) + (lane & 7) + ((lane >> 3) & 1) * 8) * 20 +                 \
            (KB) * 8 + (lane >> 4) * 4;                                        \
        uint32_t _ad = (uint32_t)__cvta_generic_to_shared(_p);                 \
        asm volatile("ldmatrix.sync.aligned.m8n8.x4.shared.b16 "               \
                     "{%0,%1,%2,%3},[%4];"                                     \
                     : "=r"((AQ)[0]), "=r"((AQ)[1]), "=r"((AQ)[2]), "=r"((AQ)[3]) \
                     : "r"(_ad));                                              \
    } while (0)

// ---------------------------------------------------------------------------
// gemm_wx: wx rows [rowOff, rowOff+Mpart) = emb @ [W_iou|W_f] + bias.
// ---------------------------------------------------------------------------
__global__ __launch_bounds__(256, 2) void gemm_wx(
    const float* __restrict__ embedTab, const int* __restrict__ xg,
    int rowOff, int Mpart)
{
    extern __shared__ char smem[];
    float (*As)[128][20] = (float (*)[128][20])smem;
    uint4 (*Bs)[16][32]  = (uint4 (*)[16][32])(smem + 3 * 128 * 80);
    const float** arows  = (const float**)(smem + 3 * 128 * 80 + 3 * 16 * 32 * 16);

    const int tid = threadIdx.x;
    const int rowBase = rowOff + blockIdx.x * 128;
    const int colBase = blockIdx.y * 128;
    const int Mend = rowOff + Mpart;

    if (tid < 128) {
        int m = rowBase + tid;
        int mc = (m < Mend) ? m : (Mend - 1);
        arows[tid] = embedTab + (size_t)xg[mc] * EMB;
    }
    __syncthreads();

    const int lane = tid & 31, warp = tid >> 5;
    const int wm = (warp & 3) * 32, wn = (warp >> 2) * 64;
    const int nbW = wn >> 3;
    const int tg = lane >> 2, tk = lane & 3;
    const int nbgBase = colBase >> 3;

    float acc[2][8][4] = {};

#define FILL_WX(ST, KC)                                                         \
    do {                                                                        \
        int _k0 = (KC) * 16;                                                    \
        _Pragma("unroll")                                                       \
        for (int _i = 0; _i < 2; ++_i) {                                        \
            int _e = tid + _i * 256, _r = _e >> 2, _c = _e & 3;                 \
            uint32_t _d = (uint32_t)__cvta_generic_to_shared(&As[ST][_r][_c*4]);\
            const float* _s = arows[_r] + _k0 + _c * 4;                         \
            int _vb = EMB - (_k0 + _c * 4);                                     \
            int _sz = (_vb >= 4) ? 16 : ((_vb > 0) ? _vb * 4 : 0);              \
            CPA16Z(_d, _s, _sz);                                                \
        }                                                                       \
        _Pragma("unroll")                                                       \
        for (int _i = 0; _i < 2; ++_i) {                                        \
            int _e = tid + _i * 256, _nb = _e >> 5, _ln = _e & 31;              \
            uint32_t _d = (uint32_t)__cvta_generic_to_shared(&Bs[ST][_nb][_ln]);\
            CPA16(_d, g_Bw_f + ((size_t)(nbgBase + _nb) * KCH_E + (KC)) * 32 + _ln); \
        }                                                                       \
        CPCOMMIT();                                                             \
    } while (0)

    FILL_WX(0, 0);
    FILL_WX(1, 1);

    for (int kch = 0; kch < KCH_E; ++kch) {
        const int s = kch % 3;
        if (kch + 1 < KCH_E) { CPWAIT(1); } else { CPWAIT(0); }
        __syncthreads();
        if (kch + 2 < KCH_E) FILL_WX((kch + 2) % 3, kch + 2);

        uint32_t a[2][2][4];
        #pragma unroll
        for (int kb = 0; kb < 2; ++kb)
            #pragma unroll
            for (int mf = 0; mf < 2; ++mf)
                LDSM_A(a[kb][mf], &As[s][0][0], wm + mf * 16, kb);

        #pragma unroll
        for (int nf = 0; nf < 8; ++nf) {
            uint4 bq = Bs[s][nbW + nf][lane];
            #pragma unroll
            for (int mf = 0; mf < 2; ++mf) {
                MMA_STEP(acc[mf][nf], a[0][mf], bq.x, bq.y);
                MMA_STEP(acc[mf][nf], a[1][mf], bq.z, bq.w);
            }
        }
    }
#undef FILL_WX

    #pragma unroll
    for (int mf = 0; mf < 2; ++mf)
        #pragma unroll
        for (int nf = 0; nf < 8; ++nf) {
            int row = rowBase + wm + mf * 16 + tg;
            int col = colBase + wn + nf * 8 + tk * 2;
            if (col < NC) {
                float b0 = g_bias[col], b1 = g_bias[col + 1];
                if (row < Mend)
                    *(float2*)(g_wx + (size_t)row * NC + col) =
                        make_float2(acc[mf][nf][0] + b0, acc[mf][nf][1] + b1);
                if (row + 8 < Mend)
                    *(float2*)(g_wx + (size_t)(row + 8) * NC + col) =
                        make_float2(acc[mf][nf][2] + b0, acc[mf][nf][3] + b1);
            }
        }
}

// ---------------------------------------------------------------------------
// level_gemm (unchanged R10/R12 configuration).
// ---------------------------------------------------------------------------
__global__ __launch_bounds__(256, 2) void level_gemm(int p0, int np)
{
    extern __shared__ char smem[];
    float (*As)[128][20] = (float (*)[128][20])smem;
    uint4 (*Bs)[16][32]  = (uint4 (*)[16][32])(smem + 3 * 128 * 80);

    const int tid = threadIdx.x;
    const bool isF = (blockIdx.y >= 8);
    const int Mrows = isF ? np * 128 : np * 64;
    const int rowBase = blockIdx.x * 128;
    if (rowBase >= Mrows) return;
    const int colBase = (isF ? (blockIdx.y - 8) : blockIdx.y) * 128;
    const int Nout = isF ? 300 : 900;
    const uint4* gB = isF ? g_Bf_f : g_Bi_f;
    float* Cout = isF ? g_Tf : g_Ti;

    const int lane = tid & 31, warp = tid >> 5;
    const int wm = (warp & 3) * 32, wn = (warp >> 2) * 64;
    const int nbW = wn >> 3;
    const int tg = lane >> 2, tk = lane & 3;
    const int nbgBase = colBase >> 3;

    const int ar = tid >> 1;
    const int ac = (tid & 1) << 1;
    int arow = rowBase + ar; if (arow >= Mrows) arow = Mrows - 1;
    const float* asrc = isF
        ? g_H  + (size_t)((2 * p0 + 1) * B_ + arow) * H_LD
        : g_Hs + (size_t)arow * H_LD;

    float acc[2][8][4] = {};

#define FILL_LV(ST, KC)                                                         \
    do {                                                                        \
        int _k0 = (KC) * 16;                                                    \
        _Pragma("unroll")                                                       \
        for (int _i = 0; _i < 2; ++_i) {                                        \
            int _c = ac + _i;                                                   \
            uint32_t _d = (uint32_t)__cvta_generic_to_shared(&As[ST][ar][_c*4]);\
            CPA16(_d, asrc + _k0 + _c * 4);                                     \
        }                                                                       \
        _Pragma("unroll")                                                       \
        for (int _i = 0; _i < 2; ++_i) {                                        \
            int _e = tid + _i * 256, _nb = _e >> 5, _ln = _e & 31;              \
            uint32_t _d = (uint32_t)__cvta_generic_to_shared(&Bs[ST][_nb][_ln]);\
            CPA16(_d, gB + ((size_t)(nbgBase + _nb) * KCH_U + (KC)) * 32 + _ln);\
        }                                                                       \
        CPCOMMIT();                                                             \
    } while (0)

    FILL_LV(0, 0);
    FILL_LV(1, 1);

    for (int kch = 0; kch < KCH_U; ++kch) {
        const int s = kch % 3;
        if (kch + 1 < KCH_U) { CPWAIT(1); } else { CPWAIT(0); }
        __syncthreads();
        if (kch + 2 < KCH_U) FILL_LV((kch + 2) % 3, kch + 2);

        uint32_t a[2][2][4];
        #pragma unroll
        for (int kb = 0; kb < 2; ++kb)
            #pragma unroll
            for (int mf = 0; mf < 2; ++mf)
                LDSM_A(a[kb][mf], &As[s][0][0], wm + mf * 16, kb);

        #pragma unroll
        for (int nf = 0; nf < 8; ++nf) {
            uint4 bq = Bs[s][nbW + nf][lane];
            #pragma unroll
            for (int mf = 0; mf < 2; ++mf) {
                MMA_STEP(acc[mf][nf], a[0][mf], bq.x, bq.y);
                MMA_STEP(acc[mf][nf], a[1][mf], bq.z, bq.w);
            }
        }
    }
#undef FILL_LV

    #pragma unroll
    for (int mf = 0; mf < 2; ++mf)
        #pragma unroll
        for (int nf = 0; nf < 8; ++nf) {
            int row = rowBase + wm + mf * 16 + tg;
            int col = colBase + wn + nf * 8 + tk * 2;
            if (col < Nout) {
                if (row < Mrows)
                    *(float2*)(Cout + (size_t)row * Nout + col) =
                        make_float2(acc[mf][nf][0], acc[mf][nf][1]);
                if (row + 8 < Mrows)
                    *(float2*)(Cout + (size_t)(row + 8) * Nout + col) =
                        make_float2(acc[mf][nf][2], acc[mf][nf][3]);
            }
        }
}

// ---------------------------------------------------------------------------
// Leaves, float4 + sibling-paired: H, C for both leaves + Hs row for d=6.
// ---------------------------------------------------------------------------
__global__ void leaf_kernel()
{
    int idx = blockIdx.x * blockDim.x + threadIdx.x;
    if (idx >= 64 * B_ * 75) return;
    int q = idx % 75;        // float4 column group (n = 4q)
    int r = idx / 75;        // j*64 + b
    int b = r % B_;
    int j = r / B_;

    float4 hs = make_float4(0.f, 0.f, 0.f, 0.f);
    #pragma unroll
    for (int s = 0; s < 2; ++s) {
        int row = (127 + 2 * j + s) * B_ + b;
        const float4* wx = (const float4*)(g_wx + (size_t)row * NC);
        float4 iv = f4sig (wx[q]);
        float4 ov = f4sig (wx[75 + q]);
        float4 uv = f4tanh(wx[150 + q]);
        float4 c4 = f4mul(iv, uv);
        float4 h4 = f4mul(ov, f4tanh(c4));
        ((float4*)(g_C + (size_t)row * HID))[q] = c4;
        ((float4*)(g_H + (size_t)row * H_LD))[q] = h4;
        hs = f4add(hs, h4);
    }
    ((float4*)(g_Hs + (size_t)r * H_LD))[q] = hs;
}

// ---------------------------------------------------------------------------
// Vectorized gate for one parent node (float4 over 4 n-values).
// ---------------------------------------------------------------------------
__device__ __forceinline__ float4 node_gate4(int p0, int pi, int b, int q, float4* cOut)
{
    int p = p0 + pi;
    const float4* wx = (const float4*)(g_wx + (size_t)(p * B_ + b) * NC);
    const float4* ti = (const float4*)(g_Ti + (size_t)(pi * B_ + b) * 900);
    float4 iv = f4sig (f4add(wx[q],       ti[q]));
    float4 ov = f4sig (f4add(wx[75 + q],  ti[75 + q]));
    float4 uv = f4tanh(f4add(wx[150 + q], ti[150 + q]));
    float4 wf = wx[225 + q];
    const float4* tl = (const float4*)(g_Tf + (size_t)((2 * pi    ) * B_ + b) * 300);
    const float4* tr = (const float4*)(g_Tf + (size_t)((2 * pi + 1) * B_ + b) * 300);
    float4 fl = f4sig(f4add(wf, tl[q]));
    float4 fr = f4sig(f4add(wf, tr[q]));
    int lc = 2 * p + 1, rc = 2 * p + 2;
    const float4* cl = (const float4*)(g_C + (size_t)(lc * B_ + b) * HID);
    const float4* cr = (const float4*)(g_C + (size_t)(rc * B_ + b) * HID);
    float4 fc = f4fma(fl, cl[q], f4mul(fr, cr[q]));
    float4 c = f4fma(iv, uv, fc);
    *cOut = c;
    return f4mul(ov, f4tanh(c));
}

__global__ void level_pw_pair(int p0, int np)
{
    int idx = blockIdx.x * blockDim.x + threadIdx.x;
    int tot = (np >> 1) * B_ * 75;
    if (idx >= tot) return;
    int q = idx % 75;
    int r = idx / 75;        // i*64 + b
    int b = r % B_;
    int i = r / B_;

    float4 cL, cR;
    float4 hL = node_gate4(p0, 2 * i,     b, q, &cL);
    float4 hR = node_gate4(p0, 2 * i + 1, b, q, &cR);

    int pL = p0 + 2 * i, pR = pL + 1;
    ((float4*)(g_C + (size_t)(pL * B_ + b) * HID))[q] = cL;
    ((float4*)(g_C + (size_t)(pR * B_ + b) * HID))[q] = cR;
    ((float4*)(g_H + (size_t)(pL * B_ + b) * H_LD))[q] = hL;
    ((float4*)(g_H + (size_t)(pR * B_ + b) * H_LD))[q] = hR;
    ((float4*)(g_Hs + (size_t)r * H_LD))[q] = f4add(hL, hR);
}

// ---------------------------------------------------------------------------
// root_out: fused root gates + output head (log_softmax over 2 classes).
// 64 blocks (one per batch) x 32 threads; warp-shuffle reduction.
// ---------------------------------------------------------------------------
__global__ __launch_bounds__(32) void root_out(
    const float* __restrict__ W_out, const float* __restrict__ b_out,
    float* __restrict__ out)
{
    const int b = blockIdx.x;
    const int tid = threadIdx.x;
    float l0 = 0.f, l1 = 0.f;
    for (int q = tid; q < 75; q += 32) {
        float4 c4;
        float4 h4 = node_gate4(0, 0, b, q, &c4);
        int n = q * 4;
        l0 = fmaf(h4.x, W_out[n * 2 + 0], l0); l1 = fmaf(h4.x, W_out[n * 2 + 1], l1);
        l0 = fmaf(h4.y, W_out[n * 2 + 2], l0); l1 = fmaf(h4.y, W_out[n * 2 + 3], l1);
        l0 = fmaf(h4.z, W_out[n * 2 + 4], l0); l1 = fmaf(h4.z, W_out[n * 2 + 5], l1);
        l0 = fmaf(h4.w, W_out[n * 2 + 6], l0); l1 = fmaf(h4.w, W_out[n * 2 + 7], l1);
    }
    #pragma unroll
    for (int o = 16; o > 0; o >>= 1) {
        l0 += __shfl_down_sync(0xffffffffu, l0, o);
        l1 += __shfl_down_sync(0xffffffffu, l1, o);
    }
    if (tid == 0) {
        l0 += b_out[0]; l1 += b_out[1];
        float m   = fmaxf(l0, l1);
        float lse = m + logf(expf(l0 - m) + expf(l1 - m));
        out[b * 2 + 0] = l0 - lse;
        out[b * 2 + 1] = l1 - lse;
    }
}

// ---------------------------------------------------------------------------
extern "C" void kernel_launch(void* const* d_in, const int* in_sizes, int n_in,
                              void* d_out, int out_size)
{
    (void)in_sizes; (void)n_in; (void)out_size;
    const int*   x     = (const int*)  d_in[0];
    const float* embed = (const float*)d_in[3];
    const float* W_iou = (const float*)d_in[4];
    const float* U_iou = (const float*)d_in[5];
    const float* b_iou = (const float*)d_in[6];
    const float* W_f   = (const float*)d_in[7];
    const float* U_f   = (const float*)d_in[8];
    const float* b_f   = (const float*)d_in[9];
    const float* W_out = (const float*)d_in[10];
    const float* b_out = (const float*)d_in[11];

    const int SMEM_WX = 3 * 128 * 80 + 3 * 16 * 32 * 16 + 128 * 8;
    const int SMEM_LV = 3 * 128 * 80 + 3 * 16 * 32 * 16;

    static cudaStream_t s2 = 0;
    static cudaEvent_t evFork = 0, evJoin = 0;
    static int inited = 0;
    if (!inited) {
        cudaFuncSetAttribute(gemm_wx,    cudaFuncAttributeMaxDynamicSharedMemorySize, SMEM_WX);
        cudaFuncSetAttribute(level_gemm, cudaFuncAttributeMaxDynamicSharedMemorySize, SMEM_LV);
        cudaStreamCreateWithFlags(&s2, cudaStreamNonBlocking);
        cudaEventCreateWithFlags(&evFork, cudaEventDisableTiming);
        cudaEventCreateWithFlags(&evJoin, cudaEventDisableTiming);
        inited = 1;
    }

    prep_kernel<<<(NBGI * KCH_U * 32 + 255) / 256, 256>>>(W_iou, W_f, U_iou, U_f, b_iou, b_f);

    // Fork: internal-node wx (rows 0..8127) on s2, overlapped with the leaf path.
    cudaEventRecord(evFork, 0);
    cudaStreamWaitEvent(s2, evFork, 0);
    gemm_wx<<<dim3(64, 10), 256, SMEM_WX, s2>>>(embed, x, 0, 127 * B_);
    cudaEventRecord(evJoin, s2);

    // Leaf path on stream 0.
    gemm_wx<<<dim3(64, 10), 256, SMEM_WX>>>(embed, x, 127 * B_, 128 * B_);
    leaf_kernel<<<(64 * B_ * 75 + 255) / 256, 256>>>();

    {
        int np = 64, p0 = 63;
        level_gemm<<<dim3(np, 11), 256, SMEM_LV>>>(p0, np);
        cudaStreamWaitEvent(0, evJoin, 0);
        level_pw_pair<<<((np / 2) * B_ * 75 + 255) / 256, 256>>>(p0, np);
    }

    for (int d = 5; d >= 1; --d) {
        int np = 1 << d;
        int p0 = np - 1;
        level_gemm<<<dim3(np, 11), 256, SMEM_LV>>>(p0, np);
        level_pw_pair<<<((np / 2) * B_ * 75 + 255) / 256, 256>>>(p0, np);
    }
    level_gemm<<<dim3(1, 11), 256, SMEM_LV>>>(0, 1);
    root_out<<<64, 32>>>(W_out, b_out, (float*)d_out);
}